// round 4
// baseline (speedup 1.0000x reference)
#include <cuda_runtime.h>

#define NN 100000
#define EE 1600000
#define GG 2000
#define BN_EPS 1e-5f

typedef unsigned long long ull;

// ---------------- scratch (static device globals; no runtime alloc) ----------------
__device__ __align__(16) float d_cat[NN * 256];   // cols [0:128)=s_raw=A@act, cols [128:256)=act (raw, pre-BN)
__device__ __align__(16) float d_act[NN * 256];   // layer-6 raw output (pre-BN), for pooling
__device__ int   d_flag;            // 1 = inputs are int64, 0 = int32
__device__ int   d_row[EE];
__device__ int   d_colv[EE];
__device__ int   d_bat[NN];
__device__ int   d_deg[NN];
__device__ float d_dinv[NN];
__device__ int   d_off[NN + 1];
__device__ int   d_cur[NN];
__device__ int   d_src[EE];
__device__ float d_nrm[EE];
__device__ float d_wsum[NN];
__device__ int   d_goff[GG + 1];
__device__ __align__(16) float d_Wcat[5 * 256 * 128 + 256 * 256];  // [Wi;Wr] per layer, [256,F] row-major
__device__ float d_stats[512];      // [0:256)=sum, [256:512)=sumsq of current act
__device__ float d_scl[256];        // BN scale of previous layer (per input feature)
__device__ float d_shl[256];        // BN shift of previous layer
__device__ float d_u[256];          // u[o] = sh @ Wi_l
__device__ float d_b2[256];         // b2[o] = b_l + sh @ Wr_l

// ---------------- dtype detection: int64 buffers have zero hi-words ----------------
__global__ void k_detect(const unsigned int* __restrict__ buf) {
    __shared__ int any;
    if (threadIdx.x == 0) any = 0;
    __syncthreads();
    const int S = 2 * EE / 2048;
    for (int k = threadIdx.x; k < 1024; k += blockDim.x) {
        unsigned int w = buf[2 * (k * S) + 1];
        if (w != 0u) atomicOr(&any, 1);
    }
    __syncthreads();
    if (threadIdx.x == 0) d_flag = (any == 0) ? 1 : 0;
}

__global__ void k_extract(const void* __restrict__ eiv) {
    int e = blockIdx.x * blockDim.x + threadIdx.x;
    if (e >= EE) return;
    int r, c;
    if (d_flag) {
        const long long* p = (const long long*)eiv;
        r = (int)p[e]; c = (int)p[EE + e];
    } else {
        const int* p = (const int*)eiv;
        r = p[e]; c = p[EE + e];
    }
    d_row[e] = r; d_colv[e] = c;
}

__global__ void k_batcvt(const void* __restrict__ bv) {
    int n = blockIdx.x * blockDim.x + threadIdx.x;
    if (n >= NN) return;
    d_bat[n] = d_flag ? (int)((const long long*)bv)[n] : ((const int*)bv)[n];
}

// ---------------- graph preprocessing ----------------
__global__ void k_zero_deg() {
    int i = blockIdx.x * blockDim.x + threadIdx.x;
    if (i < NN) d_deg[i] = 0;
}

__global__ void k_copy_x(const float* __restrict__ x) {
    int i = blockIdx.x * blockDim.x + threadIdx.x;
    if (i < NN * 32) {
        int n = i >> 5, c = i & 31;
        ((float4*)d_cat)[n * 64 + 32 + c] = ((const float4*)x)[i];
    }
}

__global__ void k_count() {
    int e = blockIdx.x * blockDim.x + threadIdx.x;
    if (e < EE) atomicAdd(&d_deg[d_colv[e]], 1);
}

__global__ void k_scan() {   // 1 block, 1024 threads: exclusive scan of deg -> off, cur, dinv
    __shared__ int ssum[1024];
    int t = threadIdx.x;
    const int C = (NN + 1023) / 1024;
    int b0 = t * C, b1 = min(b0 + C, NN);
    int s = 0;
    for (int i = b0; i < b1; i++) s += d_deg[i];
    ssum[t] = s;
    __syncthreads();
    int own = s;
    for (int off = 1; off < 1024; off <<= 1) {
        int v = (t >= off) ? ssum[t - off] : 0;
        __syncthreads();
        ssum[t] += v;
        __syncthreads();
    }
    int run = ssum[t] - own;
    for (int i = b0; i < b1; i++) {
        int d = d_deg[i];
        d_off[i] = run;
        d_cur[i] = run;
        d_dinv[i] = (d > 0) ? rsqrtf((float)d) : 0.0f;
        run += d;
    }
    if (t == 0) d_off[NN] = EE;
}

__global__ void k_fill() {
    int e = blockIdx.x * blockDim.x + threadIdx.x;
    if (e < EE) {
        int r = d_row[e];
        int c = d_colv[e];
        int p = atomicAdd(&d_cur[c], 1);
        d_src[p] = r;
        d_nrm[p] = d_dinv[r] * d_dinv[c];
    }
}

__global__ void k_wsum() {   // warp per node: wsum[i] = sum of edge norms into i
    int w = (blockIdx.x * blockDim.x + threadIdx.x) >> 5;
    int lane = threadIdx.x & 31;
    if (w >= NN) return;
    int s0 = d_off[w], s1 = d_off[w + 1];
    float s = 0.f;
    for (int k = s0 + lane; k < s1; k += 32) s += d_nrm[k];
#pragma unroll
    for (int o = 16; o > 0; o >>= 1) s += __shfl_xor_sync(0xffffffffu, s, o);
    if (lane == 0) d_wsum[w] = s;
}

__global__ void k_wcat(const float* __restrict__ Wi, const float* __restrict__ Wr,
                       const float* __restrict__ Wi6, const float* __restrict__ Wr6) {
    int i = blockIdx.x * blockDim.x + threadIdx.x;
    const int L5 = 5 * 256 * 128;
    if (i < L5) {
        int l = i >> 15;
        int rem = i & 32767;
        int k = rem >> 7, f = rem & 127;
        d_Wcat[i] = (k < 128) ? Wi[(l << 14) + (k << 7) + f]
                              : Wr[(l << 14) + ((k - 128) << 7) + f];
    } else if (i < L5 + 65536) {
        int j = i - L5;
        int k = j >> 8, f = j & 255;
        d_Wcat[i] = (k < 128) ? Wi6[(k << 8) + f] : Wr6[((k - 128) << 8) + f];
    }
}

__global__ void k_goff() {   // batch is sorted
    int n = blockIdx.x * blockDim.x + threadIdx.x;
    if (n >= NN) return;
    int bn = d_bat[n];
    int bp = (n == 0) ? -1 : d_bat[n - 1];
    for (int id = bp + 1; id <= bn; id++) d_goff[id] = n;
    if (n == NN - 1)
        for (int id = bn + 1; id <= GG; id++) d_goff[id] = NN;
}

// ---------------- BN fold helpers ----------------
__global__ void k_initbn() {     // layer 1: identity BN on input
    int f = threadIdx.x;
    if (f < 128) { d_scl[f] = 1.f; d_shl[f] = 0.f; }
}

__global__ void k_mkbn(const float* __restrict__ gamma, const float* __restrict__ beta, int F) {
    int f = threadIdx.x;
    if (f >= F) return;
    float mu = d_stats[f] * (1.f / NN);
    float var = d_stats[256 + f] * (1.f / NN) - mu * mu;
    float sc = gamma[f] * rsqrtf(var + BN_EPS);
    d_scl[f] = sc;
    d_shl[f] = beta[f] - mu * sc;
}

__global__ void k_mkub(const float* __restrict__ Wi, const float* __restrict__ Wr,
                       const float* __restrict__ b, int Nn) {
    int f = threadIdx.x;
    if (f >= Nn) return;
    float u = 0.f, bb = 0.f;
#pragma unroll 4
    for (int k = 0; k < 128; k++) {
        float sh = d_shl[k];
        u  = fmaf(sh, Wi[k * Nn + f], u);
        bb = fmaf(sh, Wr[k * Nn + f], bb);
    }
    d_u[f] = u;
    d_b2[f] = b[f] + bb;
}

__global__ void k_zstats() {
    int i = threadIdx.x;
    if (i < 512) d_stats[i] = 0.f;
}

// ---------------- SpMM: s_raw[i,:] = sum_{e: col=i} norm_e * act[row_e,:]  (warp per node) ----------------
__global__ void k_spmm() {
    int w = (blockIdx.x * blockDim.x + threadIdx.x) >> 5;
    int lane = threadIdx.x & 31;
    if (w >= NN) return;
    int s0 = d_off[w], s1 = d_off[w + 1];
    float4 acc = make_float4(0.f, 0.f, 0.f, 0.f);
    const float4* hb = (const float4*)d_cat;
    int k = s0;
    for (; k + 1 < s1; k += 2) {
        int src0 = __ldg(&d_src[k]);
        int src1 = __ldg(&d_src[k + 1]);
        float w0 = __ldg(&d_nrm[k]);
        float w1 = __ldg(&d_nrm[k + 1]);
        float4 v0 = __ldg(&hb[src0 * 64 + 32 + lane]);
        float4 v1 = __ldg(&hb[src1 * 64 + 32 + lane]);
        acc.x = fmaf(w0, v0.x, acc.x); acc.y = fmaf(w0, v0.y, acc.y);
        acc.z = fmaf(w0, v0.z, acc.z); acc.w = fmaf(w0, v0.w, acc.w);
        acc.x = fmaf(w1, v1.x, acc.x); acc.y = fmaf(w1, v1.y, acc.y);
        acc.z = fmaf(w1, v1.z, acc.z); acc.w = fmaf(w1, v1.w, acc.w);
    }
    if (k < s1) {
        int src = __ldg(&d_src[k]);
        float wt = __ldg(&d_nrm[k]);
        float4 v = __ldg(&hb[src * 64 + 32 + lane]);
        acc.x = fmaf(wt, v.x, acc.x); acc.y = fmaf(wt, v.y, acc.y);
        acc.z = fmaf(wt, v.z, acc.z); acc.w = fmaf(wt, v.w, acc.w);
    }
    ((float4*)d_cat)[w * 64 + lane] = acc;
}

// ---------------- SGEMM (f32x2 packed):
//   out = ReLU( [s_raw|act] @ (diag(scl)*Wcat) + wsum[m]*u + b2 )
//   writes act into d_cat h-half (toCat=1) or d_act (toCat=0); accumulates BN stats.
__global__ void __launch_bounds__(256) k_sgemm(int wofs, int Nn, int toCat) {
    __shared__ __align__(16) float As[2][8][256];   // duplicated pairs: row r at floats 2r,2r+1
    __shared__ __align__(16) float Bs[2][8][128];
    const float* A = d_cat;
    const float* B = d_Wcat + wofs;
    int tid = threadIdx.x;
    int bm = blockIdx.x * 128, bn = blockIdx.y * 128;
    int tx = tid & 15, ty = tid >> 4;

    ull acc2[8][4];
#pragma unroll
    for (int i = 0; i < 8; i++)
#pragma unroll
        for (int j = 0; j < 4; j++) acc2[i][j] = 0ull;

    int arow = bm + (tid >> 1);
    int akq = (tid & 1) * 4;
    int bkr = tid >> 5, bnq = (tid & 31) * 4;

    float4 av, bv;
    av = (arow < NN) ? *(const float4*)(A + arow * 256 + akq) : make_float4(0.f, 0.f, 0.f, 0.f);
    bv = *(const float4*)(B + bkr * Nn + bn + bnq);
    {
        float sc = d_scl[bkr & 127];
        bv.x *= sc; bv.y *= sc; bv.z *= sc; bv.w *= sc;
    }
    *(float2*)&As[0][akq + 0][2 * (tid >> 1)] = make_float2(av.x, av.x);
    *(float2*)&As[0][akq + 1][2 * (tid >> 1)] = make_float2(av.y, av.y);
    *(float2*)&As[0][akq + 2][2 * (tid >> 1)] = make_float2(av.z, av.z);
    *(float2*)&As[0][akq + 3][2 * (tid >> 1)] = make_float2(av.w, av.w);
    *(float4*)&Bs[0][bkr][bnq] = bv;
    __syncthreads();

    int buf = 0;
    for (int ks = 0; ks < 32; ks++) {
        int k0n = (ks + 1) * 8;
        float scn = 0.f;
        if (ks < 31) {
            av = (arow < NN) ? *(const float4*)(A + arow * 256 + k0n + akq)
                             : make_float4(0.f, 0.f, 0.f, 0.f);
            bv = *(const float4*)(B + (k0n + bkr) * Nn + bn + bnq);
            scn = d_scl[(k0n + bkr) & 127];
        }
#pragma unroll
        for (int k = 0; k < 8; k++) {
            ull a2[8], b2[4];
            {
                ulonglong2 t0 = *(const ulonglong2*)&As[buf][k][8 * ty];
                ulonglong2 t1 = *(const ulonglong2*)&As[buf][k][8 * ty + 4];
                ulonglong2 t2 = *(const ulonglong2*)&As[buf][k][128 + 8 * ty];
                ulonglong2 t3 = *(const ulonglong2*)&As[buf][k][128 + 8 * ty + 4];
                a2[0] = t0.x; a2[1] = t0.y; a2[2] = t1.x; a2[3] = t1.y;
                a2[4] = t2.x; a2[5] = t2.y; a2[6] = t3.x; a2[7] = t3.y;
                ulonglong2 u0 = *(const ulonglong2*)&Bs[buf][k][tx * 4];
                ulonglong2 u1 = *(const ulonglong2*)&Bs[buf][k][64 + tx * 4];
                b2[0] = u0.x; b2[1] = u0.y; b2[2] = u1.x; b2[3] = u1.y;
            }
#pragma unroll
            for (int i = 0; i < 8; i++)
#pragma unroll
                for (int j = 0; j < 4; j++)
                    asm("fma.rn.f32x2 %0, %1, %2, %0;"
                        : "+l"(acc2[i][j]) : "l"(a2[i]), "l"(b2[j]));
        }
        if (ks < 31) {
            int nb = buf ^ 1;
            bv.x *= scn; bv.y *= scn; bv.z *= scn; bv.w *= scn;
            *(float2*)&As[nb][akq + 0][2 * (tid >> 1)] = make_float2(av.x, av.x);
            *(float2*)&As[nb][akq + 1][2 * (tid >> 1)] = make_float2(av.y, av.y);
            *(float2*)&As[nb][akq + 2][2 * (tid >> 1)] = make_float2(av.z, av.z);
            *(float2*)&As[nb][akq + 3][2 * (tid >> 1)] = make_float2(av.w, av.w);
            *(float4*)&Bs[nb][bkr][bnq] = bv;
            __syncthreads();
            buf = nb;
        }
    }

    // epilogue: columns this thread owns (pairs)
    int cb[4];
    cb[0] = bn + tx * 4;  cb[1] = bn + tx * 4 + 2;
    cb[2] = bn + 64 + tx * 4;  cb[3] = bn + 64 + tx * 4 + 2;
    float ub[4][2], bb[4][2];
#pragma unroll
    for (int j = 0; j < 4; j++) {
        ub[j][0] = d_u[cb[j]];     ub[j][1] = d_u[cb[j] + 1];
        bb[j][0] = d_b2[cb[j]];    bb[j][1] = d_b2[cb[j] + 1];
    }
    float cs[4][2] = {}, cq[4][2] = {};
#pragma unroll
    for (int i = 0; i < 8; i++) {
        int m = bm + ((i < 4) ? (ty * 4 + i) : (64 + ty * 4 + i - 4));
        if (m < NN) {
            float wsm = d_wsum[m];
#pragma unroll
            for (int j = 0; j < 4; j++) {
                float2 v2 = *(float2*)&acc2[i][j];
                float v0 = v2.x + bb[j][0] + wsm * ub[j][0];
                float v1 = v2.y + bb[j][1] + wsm * ub[j][1];
                v0 = (v0 > 0.f) ? v0 : 0.f;
                v1 = (v1 > 0.f) ? v1 : 0.f;
                if (toCat) *(float2*)&d_cat[m * 256 + 128 + cb[j]] = make_float2(v0, v1);
                else       *(float2*)&d_act[m * 256 + cb[j]] = make_float2(v0, v1);
                cs[j][0] += v0; cq[j][0] += v0 * v0;
                cs[j][1] += v1; cq[j][1] += v1 * v1;
            }
        }
    }
#pragma unroll
    for (int j = 0; j < 4; j++) {
        atomicAdd(&d_stats[cb[j]], cs[j][0]);
        atomicAdd(&d_stats[cb[j] + 1], cs[j][1]);
        atomicAdd(&d_stats[256 + cb[j]], cq[j][0]);
        atomicAdd(&d_stats[256 + cb[j] + 1], cq[j][1]);
    }
}

// ---------------- global add pool: out[g,f] = scl[f]*sum(act6) + cnt_g*shl[f] ----------------
__global__ void k_pool(float* __restrict__ out) {
    int g = blockIdx.x, f = threadIdx.x;
    int n0 = d_goff[g], n1 = d_goff[g + 1];
    float s = 0.f;
    for (int n = n0; n < n1; n++) s += d_act[n * 256 + f];
    out[g * 256 + f] = d_scl[f] * s + (float)(n1 - n0) * d_shl[f];
}

// ---------------- launch ----------------
extern "C" void kernel_launch(void* const* d_in, const int* in_sizes, int n_in,
                              void* d_out, int out_size) {
    const float* x   = (const float*)d_in[0];
    const void*  ei  = d_in[1];
    const void*  bat = d_in[2];
    const float* Wi  = (const float*)d_in[3];
    const float* Wr  = (const float*)d_in[4];
    const float* b   = (const float*)d_in[5];
    const float* g   = (const float*)d_in[6];
    const float* be  = (const float*)d_in[7];
    const float* Wi6 = (const float*)d_in[8];
    const float* Wr6 = (const float*)d_in[9];
    const float* b6  = (const float*)d_in[10];
    const float* g6  = (const float*)d_in[11];
    const float* be6 = (const float*)d_in[12];
    float* out = (float*)d_out;

    k_detect<<<1, 256>>>((const unsigned int*)ei);
    k_extract<<<(EE + 255) / 256, 256>>>(ei);
    k_batcvt<<<(NN + 255) / 256, 256>>>(bat);

    k_zero_deg<<<(NN + 255) / 256, 256>>>();
    k_copy_x<<<(NN * 32 + 255) / 256, 256>>>(x);
    k_count<<<(EE + 255) / 256, 256>>>();
    k_scan<<<1, 1024>>>();
    k_fill<<<(EE + 255) / 256, 256>>>();
    k_wsum<<<(NN + 7) / 8, 256>>>();
    k_wcat<<<(5 * 32768 + 65536 + 255) / 256, 256>>>(Wi, Wr, Wi6, Wr6);
    k_goff<<<(NN + 255) / 256, 256>>>();

    const int mblocks = (NN + 127) / 128;
    for (int l = 0; l < 5; l++) {
        k_spmm<<<(NN + 7) / 8, 256>>>();
        if (l == 0) k_initbn<<<1, 128>>>();
        else        k_mkbn<<<1, 256>>>(g + (l - 1) * 128, be + (l - 1) * 128, 128);
        k_mkub<<<1, 256>>>(Wi + l * 16384, Wr + l * 16384, b + l * 128, 128);
        k_zstats<<<1, 512>>>();
        k_sgemm<<<dim3(mblocks, 1), 256>>>(l * 32768, 128, 1);
    }
    // layer 6 (F_OUT = 256)
    k_spmm<<<(NN + 7) / 8, 256>>>();
    k_mkbn<<<1, 256>>>(g + 4 * 128, be + 4 * 128, 128);
    k_mkub<<<1, 256>>>(Wi6, Wr6, b6, 256);
    k_zstats<<<1, 512>>>();
    k_sgemm<<<dim3(mblocks, 2), 256>>>(5 * 32768, 256, 0);

    k_mkbn<<<1, 256>>>(g6, be6, 256);
    k_pool<<<GG, 256>>>(out);
}

// round 5
// speedup vs baseline: 1.4045x; 1.4045x over previous
#include <cuda_runtime.h>

#define NN 100000
#define EE 1600000
#define GG 2000
#define BN_EPS 1e-5f

// ---------------- scratch (static device globals; no runtime alloc) ----------------
__device__ __align__(16) float d_cat[NN * 256];   // cols [0:128)=s_raw=A@act, cols [128:256)=act (raw)
__device__ __align__(16) float d_act[NN * 256];   // layer-6 raw output (pre-BN), for pooling
__device__ int   d_flag;            // 1 = inputs are int64, 0 = int32
__device__ int   d_row[EE];
__device__ int   d_colv[EE];
__device__ int   d_deg[NN];
__device__ float d_dinv[NN];
__device__ int   d_off[NN + 1];
__device__ int   d_cur[NN];
__device__ int   d_src[EE];
__device__ float d_nrm[EE];
__device__ float d_wsum[NN];
__device__ int   d_goff[GG + 1];
__device__ __align__(16) float d_Wcat[5 * 256 * 128 + 256 * 256];  // [Wi;Wr] per layer, [256,F] row-major
__device__ float d_stats[512];      // [0:256)=sum, [256:512)=sumsq of current raw act
__device__ float d_scl[256];        // BN scale of previous layer (per input feature)
__device__ float d_shl[256];        // BN shift of previous layer
__device__ float d_u[256];          // u[o] = shl @ Wi_l
__device__ float d_b2[256];         // b2[o] = b_l + shl @ Wr_l

// ---------------- dtype detection: int64 buffers have zero hi-words ----------------
__global__ void k_detect(const unsigned int* __restrict__ buf) {
    __shared__ int any;
    if (threadIdx.x == 0) any = 0;
    __syncthreads();
    const int S = 2 * EE / 2048;
    for (int k = threadIdx.x; k < 1024; k += blockDim.x) {
        unsigned int w = buf[2 * (k * S) + 1];
        if (w != 0u) atomicOr(&any, 1);
    }
    __syncthreads();
    if (threadIdx.x == 0) d_flag = (any == 0) ? 1 : 0;
}

__global__ void k_extract(const void* __restrict__ eiv) {   // also zeroes d_deg
    int e = blockIdx.x * blockDim.x + threadIdx.x;
    if (e >= EE) return;
    if (e < NN) d_deg[e] = 0;
    int r, c;
    if (d_flag) {
        const long long* p = (const long long*)eiv;
        r = (int)p[e]; c = (int)p[EE + e];
    } else {
        const int* p = (const int*)eiv;
        r = p[e]; c = p[EE + e];
    }
    d_row[e] = r; d_colv[e] = c;
}

// ---------------- graph preprocessing ----------------
__global__ void k_copy_x(const float* __restrict__ x) {
    int i = blockIdx.x * blockDim.x + threadIdx.x;
    if (i < NN * 32) {
        int n = i >> 5, c = i & 31;
        ((float4*)d_cat)[n * 64 + 32 + c] = ((const float4*)x)[i];
    }
}

__global__ void k_count() {
    int e = blockIdx.x * blockDim.x + threadIdx.x;
    if (e < EE) atomicAdd(&d_deg[d_colv[e]], 1);
}

__global__ void k_scan() {   // 1 block, 1024 threads: exclusive scan of deg -> off, cur, dinv
    __shared__ int ssum[1024];
    int t = threadIdx.x;
    const int C = (NN + 1023) / 1024;
    int b0 = t * C, b1 = min(b0 + C, NN);
    int s = 0;
    for (int i = b0; i < b1; i++) s += d_deg[i];
    ssum[t] = s;
    __syncthreads();
    int own = s;
    for (int off = 1; off < 1024; off <<= 1) {
        int v = (t >= off) ? ssum[t - off] : 0;
        __syncthreads();
        ssum[t] += v;
        __syncthreads();
    }
    int run = ssum[t] - own;
    for (int i = b0; i < b1; i++) {
        int d = d_deg[i];
        d_off[i] = run;
        d_cur[i] = run;
        d_dinv[i] = (d > 0) ? rsqrtf((float)d) : 0.0f;
        run += d;
    }
    if (t == 0) d_off[NN] = EE;
}

__global__ void k_fill() {
    int e = blockIdx.x * blockDim.x + threadIdx.x;
    if (e < EE) {
        int r = d_row[e];
        int c = d_colv[e];
        int p = atomicAdd(&d_cur[c], 1);
        d_src[p] = r;
        d_nrm[p] = d_dinv[r] * d_dinv[c];
    }
}

__global__ void k_wsum() {   // warp per node: wsum[i] = sum of edge norms into i
    int w = (blockIdx.x * blockDim.x + threadIdx.x) >> 5;
    int lane = threadIdx.x & 31;
    if (w >= NN) return;
    int s0 = d_off[w], s1 = d_off[w + 1];
    float s = 0.f;
    for (int k = s0 + lane; k < s1; k += 32) s += d_nrm[k];
#pragma unroll
    for (int o = 16; o > 0; o >>= 1) s += __shfl_xor_sync(0xffffffffu, s, o);
    if (lane == 0) d_wsum[w] = s;
}

__global__ void k_wcat(const float* __restrict__ Wi, const float* __restrict__ Wr,
                       const float* __restrict__ Wi6, const float* __restrict__ Wr6) {
    int i = blockIdx.x * blockDim.x + threadIdx.x;
    const int L5 = 5 * 256 * 128;
    if (i < L5) {
        int l = i >> 15;
        int rem = i & 32767;
        int k = rem >> 7, f = rem & 127;
        d_Wcat[i] = (k < 128) ? Wi[(l << 14) + (k << 7) + f]
                              : Wr[(l << 14) + ((k - 128) << 7) + f];
    } else if (i < L5 + 65536) {
        int j = i - L5;
        int k = j >> 8, f = j & 255;
        d_Wcat[i] = (k < 128) ? Wi6[(k << 8) + f] : Wr6[((k - 128) << 8) + f];
    }
}

__global__ void k_goff(const void* __restrict__ bv) {   // batch sorted; reads raw input
    int n = blockIdx.x * blockDim.x + threadIdx.x;
    if (n >= NN) return;
    int bn, bp;
    if (d_flag) {
        const long long* p = (const long long*)bv;
        bn = (int)p[n]; bp = (n == 0) ? -1 : (int)p[n - 1];
    } else {
        const int* p = (const int*)bv;
        bn = p[n]; bp = (n == 0) ? -1 : p[n - 1];
    }
    for (int id = bp + 1; id <= bn; id++) d_goff[id] = n;
    if (n == NN - 1)
        for (int id = bn + 1; id <= GG; id++) d_goff[id] = NN;
}

// ---------------- BN fold helpers ----------------
__global__ void k_initbn() {     // layer 1: identity BN on input
    int f = threadIdx.x;
    if (f < 128) { d_scl[f] = 1.f; d_shl[f] = 0.f; }
}

__global__ void k_mkbn(const float* __restrict__ gamma, const float* __restrict__ beta, int F) {
    int f = threadIdx.x;
    if (f >= F) return;
    float mu = d_stats[f] * (1.f / NN);
    float var = d_stats[256 + f] * (1.f / NN) - mu * mu;
    float sc = gamma[f] * rsqrtf(var + BN_EPS);
    d_scl[f] = sc;
    d_shl[f] = beta[f] - mu * sc;
}

__global__ void k_mkub(const float* __restrict__ Wi, const float* __restrict__ Wr,
                       const float* __restrict__ b, int Nn) {
    int f = threadIdx.x;
    if (f >= Nn) return;
    float u = 0.f, bb = 0.f;
#pragma unroll 4
    for (int k = 0; k < 128; k++) {
        float sh = d_shl[k];
        u  = fmaf(sh, Wi[k * Nn + f], u);
        bb = fmaf(sh, Wr[k * Nn + f], bb);
    }
    d_u[f] = u;
    d_b2[f] = b[f] + bb;
}

__global__ void k_zstats() {
    int i = threadIdx.x;
    if (i < 512) d_stats[i] = 0.f;
}

// ---------------- SpMM: s_raw[i,:] = sum_{e: col=i} norm_e * act[row_e,:]  (warp per node) ----------------
__global__ void k_spmm() {
    int w = (blockIdx.x * blockDim.x + threadIdx.x) >> 5;
    int lane = threadIdx.x & 31;
    if (w >= NN) return;
    int s0 = d_off[w], s1 = d_off[w + 1];
    float4 acc = make_float4(0.f, 0.f, 0.f, 0.f);
    const float4* hb = (const float4*)d_cat;
    int k = s0;
    for (; k + 1 < s1; k += 2) {
        int src0 = __ldg(&d_src[k]);
        int src1 = __ldg(&d_src[k + 1]);
        float w0 = __ldg(&d_nrm[k]);
        float w1 = __ldg(&d_nrm[k + 1]);
        float4 v0 = __ldg(&hb[src0 * 64 + 32 + lane]);
        float4 v1 = __ldg(&hb[src1 * 64 + 32 + lane]);
        acc.x = fmaf(w0, v0.x, acc.x); acc.y = fmaf(w0, v0.y, acc.y);
        acc.z = fmaf(w0, v0.z, acc.z); acc.w = fmaf(w0, v0.w, acc.w);
        acc.x = fmaf(w1, v1.x, acc.x); acc.y = fmaf(w1, v1.y, acc.y);
        acc.z = fmaf(w1, v1.z, acc.z); acc.w = fmaf(w1, v1.w, acc.w);
    }
    if (k < s1) {
        int src = __ldg(&d_src[k]);
        float wt = __ldg(&d_nrm[k]);
        float4 v = __ldg(&hb[src * 64 + 32 + lane]);
        acc.x = fmaf(wt, v.x, acc.x); acc.y = fmaf(wt, v.y, acc.y);
        acc.z = fmaf(wt, v.z, acc.z); acc.w = fmaf(wt, v.w, acc.w);
    }
    ((float4*)d_cat)[w * 64 + lane] = acc;
}

// ---------------- SGEMM (scalar FFMA, R3-proven) + BN-fold epilogue:
//   out = ReLU( [s_raw|act] @ (diag(scl)*Wcat) + wsum[m]*u + b2 )
//   writes raw act to d_cat h-half (toCat=1) or d_act (toCat=0); accumulates BN stats.
__global__ void __launch_bounds__(256) k_sgemm(int wofs, int Nn, int toCat) {
    __shared__ float As[2][8][128];
    __shared__ float Bs[2][8][128];
    const float* A = d_cat;
    const float* B = d_Wcat + wofs;
    int tid = threadIdx.x;
    int bm = blockIdx.x * 128, bn = blockIdx.y * 128;
    int tx = tid & 15, ty = tid >> 4;

    float acc[8][8];
#pragma unroll
    for (int i = 0; i < 8; i++)
#pragma unroll
        for (int j = 0; j < 8; j++) acc[i][j] = 0.f;

    int arow = bm + (tid >> 1);
    int akq = (tid & 1) * 4;
    int bkr = tid >> 5, bnq = (tid & 31) * 4;

    float4 av, bv;
    av = (arow < NN) ? *(const float4*)(A + arow * 256 + akq) : make_float4(0.f, 0.f, 0.f, 0.f);
    bv = *(const float4*)(B + bkr * Nn + bn + bnq);
    {
        float sc = d_scl[bkr & 127];
        bv.x *= sc; bv.y *= sc; bv.z *= sc; bv.w *= sc;
    }
    As[0][akq + 0][tid >> 1] = av.x;
    As[0][akq + 1][tid >> 1] = av.y;
    As[0][akq + 2][tid >> 1] = av.z;
    As[0][akq + 3][tid >> 1] = av.w;
    *(float4*)&Bs[0][bkr][bnq] = bv;
    __syncthreads();

    int buf = 0;
    for (int ks = 0; ks < 32; ks++) {
        int k0n = (ks + 1) * 8;
        float scn = 0.f;
        if (ks < 31) {
            av = (arow < NN) ? *(const float4*)(A + arow * 256 + k0n + akq)
                             : make_float4(0.f, 0.f, 0.f, 0.f);
            bv = *(const float4*)(B + (k0n + bkr) * Nn + bn + bnq);
            scn = d_scl[(k0n + bkr) & 127];
        }
#pragma unroll
        for (int k = 0; k < 8; k++) {
            float a[8], b[8];
            *(float4*)&a[0] = *(const float4*)&As[buf][k][ty * 4];
            *(float4*)&a[4] = *(const float4*)&As[buf][k][64 + ty * 4];
            *(float4*)&b[0] = *(const float4*)&Bs[buf][k][tx * 4];
            *(float4*)&b[4] = *(const float4*)&Bs[buf][k][64 + tx * 4];
#pragma unroll
            for (int i = 0; i < 8; i++)
#pragma unroll
                for (int j = 0; j < 8; j++) acc[i][j] = fmaf(a[i], b[j], acc[i][j]);
        }
        if (ks < 31) {
            int nb = buf ^ 1;
            bv.x *= scn; bv.y *= scn; bv.z *= scn; bv.w *= scn;
            As[nb][akq + 0][tid >> 1] = av.x;
            As[nb][akq + 1][tid >> 1] = av.y;
            As[nb][akq + 2][tid >> 1] = av.z;
            As[nb][akq + 3][tid >> 1] = av.w;
            *(float4*)&Bs[nb][bkr][bnq] = bv;
            __syncthreads();
            buf = nb;
        }
    }

    // epilogue: fold rank-1 term + bias, ReLU, write raw act, accumulate BN stats
    int col[8];
    float uu[8], bb2[8], cs[8], cq[8];
#pragma unroll
    for (int j = 0; j < 8; j++) {
        col[j] = bn + ((j < 4) ? (tx * 4 + j) : (64 + tx * 4 + j - 4));
        uu[j] = d_u[col[j]];
        bb2[j] = d_b2[col[j]];
        cs[j] = 0.f; cq[j] = 0.f;
    }
#pragma unroll
    for (int i = 0; i < 8; i++) {
        int m = bm + ((i < 4) ? (ty * 4 + i) : (64 + ty * 4 + i - 4));
        if (m < NN) {
            float wsm = d_wsum[m];
#pragma unroll
            for (int j = 0; j < 8; j++) {
                float v = acc[i][j] + bb2[j] + wsm * uu[j];
                v = (v > 0.f) ? v : 0.f;
                if (toCat) d_cat[m * 256 + 128 + col[j]] = v;
                else       d_act[m * Nn + col[j]] = v;
                cs[j] += v;
                cq[j] += v * v;
            }
        }
    }
#pragma unroll
    for (int j = 0; j < 8; j++) {
        atomicAdd(&d_stats[col[j]], cs[j]);
        atomicAdd(&d_stats[256 + col[j]], cq[j]);
    }
}

// ---------------- global add pool: out[g,f] = scl[f]*sum(act6) + cnt_g*shl[f] ----------------
__global__ void k_pool(float* __restrict__ out) {
    int g = blockIdx.x, f = threadIdx.x;
    int n0 = d_goff[g], n1 = d_goff[g + 1];
    float s = 0.f;
    for (int n = n0; n < n1; n++) s += d_act[n * 256 + f];
    out[g * 256 + f] = d_scl[f] * s + (float)(n1 - n0) * d_shl[f];
}

// ---------------- launch ----------------
extern "C" void kernel_launch(void* const* d_in, const int* in_sizes, int n_in,
                              void* d_out, int out_size) {
    const float* x   = (const float*)d_in[0];
    const void*  ei  = d_in[1];
    const void*  bat = d_in[2];
    const float* Wi  = (const float*)d_in[3];
    const float* Wr  = (const float*)d_in[4];
    const float* b   = (const float*)d_in[5];
    const float* g   = (const float*)d_in[6];
    const float* be  = (const float*)d_in[7];
    const float* Wi6 = (const float*)d_in[8];
    const float* Wr6 = (const float*)d_in[9];
    const float* b6  = (const float*)d_in[10];
    const float* g6  = (const float*)d_in[11];
    const float* be6 = (const float*)d_in[12];
    float* out = (float*)d_out;

    k_detect<<<1, 256>>>((const unsigned int*)ei);
    k_extract<<<(EE + 255) / 256, 256>>>(ei);
    k_goff<<<(NN + 255) / 256, 256>>>(bat);
    k_copy_x<<<(NN * 32 + 255) / 256, 256>>>(x);
    k_count<<<(EE + 255) / 256, 256>>>();
    k_scan<<<1, 1024>>>();
    k_fill<<<(EE + 255) / 256, 256>>>();
    k_wsum<<<(NN + 7) / 8, 256>>>();
    k_wcat<<<(5 * 32768 + 65536 + 255) / 256, 256>>>(Wi, Wr, Wi6, Wr6);

    const int mblocks = (NN + 127) / 128;
    for (int l = 0; l < 5; l++) {
        k_spmm<<<(NN + 7) / 8, 256>>>();
        if (l == 0) k_initbn<<<1, 128>>>();
        else        k_mkbn<<<1, 256>>>(g + (l - 1) * 128, be + (l - 1) * 128, 128);
        k_mkub<<<1, 256>>>(Wi + l * 16384, Wr + l * 16384, b + l * 128, 128);
        k_zstats<<<1, 512>>>();
        k_sgemm<<<dim3(mblocks, 1), 256>>>(l * 32768, 128, 1);
    }
    // layer 6 (F_OUT = 256)
    k_spmm<<<(NN + 7) / 8, 256>>>();
    k_mkbn<<<1, 256>>>(g + 4 * 128, be + 4 * 128, 128);
    k_mkub<<<1, 256>>>(Wi6, Wr6, b6, 256);
    k_zstats<<<1, 512>>>();
    k_sgemm<<<dim3(mblocks, 2), 256>>>(5 * 32768, 256, 0);

    k_mkbn<<<1, 256>>>(g6, be6, 256);
    k_pool<<<GG, 256>>>(out);
}

// round 7
// speedup vs baseline: 1.9475x; 1.3866x over previous
#include <cuda_runtime.h>

#define NN 100000
#define EE 1600000
#define GG 2000
#define BN_EPS 1e-5f

// ---------------- scratch (static device globals; no runtime alloc) ----------------
__device__ __align__(16) float d_cat[NN * 256];   // cols [0:128)=s_raw=A@act, cols [128:256)=act (raw)
__device__ __align__(16) float d_act[NN * 256];   // layer-6 raw output (pre-BN), for pooling
__device__ int   d_flag;            // 1 = inputs are int64, 0 = int32
__device__ int   d_row[EE];
__device__ int   d_colv[EE];
__device__ int   d_deg[NN];
__device__ float d_dinv[NN];
__device__ int   d_off[NN + 1];
__device__ int   d_cur[NN];
__device__ int   d_src[EE];
__device__ float d_nrm[EE];
__device__ float d_wsum[NN];
__device__ int   d_goff[GG + 1];
__device__ __align__(16) float d_Wcat[5 * 256 * 128 + 256 * 256];  // [Wi;Wr] per layer, [256,F] row-major
__device__ __align__(16) float d_Wscl[256 * 256];  // current layer's diag(scl) * Wcat
__device__ float d_stats[512];      // [0:256)=sum, [256:512)=sumsq of current raw act
__device__ float d_scl[256];        // BN scale of previous layer (per input feature)
__device__ float d_shl[256];        // BN shift of previous layer
__device__ float d_u[256];          // u[o] = shl @ Wi_l
__device__ float d_b2[256];         // b2[o] = b_l + shl @ Wr_l

// ---------------- dtype detection: int64 buffers have zero hi-words ----------------
__global__ void k_detect(const unsigned int* __restrict__ buf) {
    __shared__ int any;
    if (threadIdx.x == 0) any = 0;
    __syncthreads();
    const int S = 2 * EE / 2048;
    for (int k = threadIdx.x; k < 1024; k += blockDim.x) {
        unsigned int w = buf[2 * (k * S) + 1];
        if (w != 0u) atomicOr(&any, 1);
    }
    __syncthreads();
    if (threadIdx.x == 0) d_flag = (any == 0) ? 1 : 0;
}

// extract edges + zero deg + copy x into d_cat h-half (one kernel, 3.2M threads)
__global__ void k_extract_copy(const void* __restrict__ eiv, const float* __restrict__ x) {
    int i = blockIdx.x * blockDim.x + threadIdx.x;
    if (i < NN * 32) {
        int n = i >> 5, c = i & 31;
        ((float4*)d_cat)[n * 64 + 32 + c] = ((const float4*)x)[i];
    }
    if (i < NN) d_deg[i] = 0;
    if (i < EE) {
        int r, c;
        if (d_flag) {
            const long long* p = (const long long*)eiv;
            r = (int)p[i]; c = (int)p[EE + i];
        } else {
            const int* p = (const int*)eiv;
            r = p[i]; c = p[EE + i];
        }
        d_row[i] = r; d_colv[i] = c;
    }
}

__global__ void k_count() {
    int e = blockIdx.x * blockDim.x + threadIdx.x;
    if (e < EE) atomicAdd(&d_deg[d_colv[e]], 1);
}

__global__ void k_scan() {   // 1 block, 1024 threads: exclusive scan of deg -> off, cur, dinv
    __shared__ int ssum[1024];
    int t = threadIdx.x;
    const int C = (NN + 1023) / 1024;
    int b0 = t * C, b1 = min(b0 + C, NN);
    int s = 0;
    for (int i = b0; i < b1; i++) s += d_deg[i];
    ssum[t] = s;
    __syncthreads();
    int own = s;
    for (int off = 1; off < 1024; off <<= 1) {
        int v = (t >= off) ? ssum[t - off] : 0;
        __syncthreads();
        ssum[t] += v;
        __syncthreads();
    }
    int run = ssum[t] - own;
    for (int i = b0; i < b1; i++) {
        int d = d_deg[i];
        d_off[i] = run;
        d_cur[i] = run;
        d_dinv[i] = (d > 0) ? rsqrtf((float)d) : 0.0f;
        run += d;
    }
    if (t == 0) d_off[NN] = EE;
}

__global__ void k_fill() {
    int e = blockIdx.x * blockDim.x + threadIdx.x;
    if (e < EE) {
        int r = d_row[e];
        int c = d_colv[e];
        int p = atomicAdd(&d_cur[c], 1);
        d_src[p] = r;
        d_nrm[p] = d_dinv[r] * d_dinv[c];
    }
}

__global__ void k_wsum() {   // warp per node: wsum[i] = sum of edge norms into i
    int w = (blockIdx.x * blockDim.x + threadIdx.x) >> 5;
    int lane = threadIdx.x & 31;
    if (w >= NN) return;
    int s0 = d_off[w], s1 = d_off[w + 1];
    float s = 0.f;
    for (int k = s0 + lane; k < s1; k += 32) s += d_nrm[k];
#pragma unroll
    for (int o = 16; o > 0; o >>= 1) s += __shfl_xor_sync(0xffffffffu, s, o);
    if (lane == 0) d_wsum[w] = s;
}

__global__ void k_wcat(const float* __restrict__ Wi, const float* __restrict__ Wr,
                       const float* __restrict__ Wi6, const float* __restrict__ Wr6) {
    int i = blockIdx.x * blockDim.x + threadIdx.x;
    const int L5 = 5 * 256 * 128;
    if (i < L5) {
        int l = i >> 15;
        int rem = i & 32767;
        int k = rem >> 7, f = rem & 127;
        d_Wcat[i] = (k < 128) ? Wi[(l << 14) + (k << 7) + f]
                              : Wr[(l << 14) + ((k - 128) << 7) + f];
    } else if (i < L5 + 65536) {
        int j = i - L5;
        int k = j >> 8, f = j & 255;
        d_Wcat[i] = (k < 128) ? Wi6[(k << 8) + f] : Wr6[((k - 128) << 8) + f];
    }
}

__global__ void k_goff(const void* __restrict__ bv) {   // batch sorted; reads raw input
    int n = blockIdx.x * blockDim.x + threadIdx.x;
    if (n >= NN) return;
    int bn, bp;
    if (d_flag) {
        const long long* p = (const long long*)bv;
        bn = (int)p[n]; bp = (n == 0) ? -1 : (int)p[n - 1];
    } else {
        const int* p = (const int*)bv;
        bn = p[n]; bp = (n == 0) ? -1 : p[n - 1];
    }
    for (int id = bp + 1; id <= bn; id++) d_goff[id] = n;
    if (n == NN - 1)
        for (int id = bn + 1; id <= GG; id++) d_goff[id] = NN;
}

// ---------------- BN fold helpers ----------------
__global__ void k_initbn() {     // layer 1: identity BN on input
    int f = threadIdx.x;
    if (f < 128) { d_scl[f] = 1.f; d_shl[f] = 0.f; }
}

__global__ void k_mkbn(const float* __restrict__ gamma, const float* __restrict__ beta, int F) {
    int f = threadIdx.x;
    if (f >= F) return;
    float mu = d_stats[f] * (1.f / NN);
    float var = d_stats[256 + f] * (1.f / NN) - mu * mu;
    float sc = gamma[f] * rsqrtf(var + BN_EPS);
    d_scl[f] = sc;
    d_shl[f] = beta[f] - mu * sc;
}

// B_scaled[k][n] = scl[k & 127] * Wcat[k][n]
__global__ void k_scaleB(int wofs, int Nn) {
    int i = blockIdx.x * blockDim.x + threadIdx.x;
    if (i < 256 * Nn) d_Wscl[i] = d_scl[(i / Nn) & 127] * d_Wcat[wofs + i];
}

// u = shl @ Wi, b2 = b + shl @ Wr; also zeroes stats for this layer
__global__ void k_mkub(const float* __restrict__ Wi, const float* __restrict__ Wr,
                       const float* __restrict__ b, int Nn) {
    int f = threadIdx.x;
    d_stats[f] = 0.f;
    d_stats[256 + f] = 0.f;
    if (f >= Nn) return;
    float u = 0.f, bb = 0.f;
#pragma unroll 4
    for (int k = 0; k < 128; k++) {
        float sh = d_shl[k];
        u  = fmaf(sh, Wi[k * Nn + f], u);
        bb = fmaf(sh, Wr[k * Nn + f], bb);
    }
    d_u[f] = u;
    d_b2[f] = b[f] + bb;
}

// ---------------- SpMM: s_raw[i,:] = sum_{e: col=i} norm_e * act[row_e,:]  (warp per node) ----------------
__global__ void k_spmm() {
    int w = (blockIdx.x * blockDim.x + threadIdx.x) >> 5;
    int lane = threadIdx.x & 31;
    if (w >= NN) return;
    int s0 = d_off[w], s1 = d_off[w + 1];
    float4 acc = make_float4(0.f, 0.f, 0.f, 0.f);
    const float4* hb = (const float4*)d_cat;
    int k = s0;
    for (; k + 1 < s1; k += 2) {
        int src0 = __ldg(&d_src[k]);
        int src1 = __ldg(&d_src[k + 1]);
        float w0 = __ldg(&d_nrm[k]);
        float w1 = __ldg(&d_nrm[k + 1]);
        float4 v0 = __ldg(&hb[src0 * 64 + 32 + lane]);
        float4 v1 = __ldg(&hb[src1 * 64 + 32 + lane]);
        acc.x = fmaf(w0, v0.x, acc.x); acc.y = fmaf(w0, v0.y, acc.y);
        acc.z = fmaf(w0, v0.z, acc.z); acc.w = fmaf(w0, v0.w, acc.w);
        acc.x = fmaf(w1, v1.x, acc.x); acc.y = fmaf(w1, v1.y, acc.y);
        acc.z = fmaf(w1, v1.z, acc.z); acc.w = fmaf(w1, v1.w, acc.w);
    }
    if (k < s1) {
        int src = __ldg(&d_src[k]);
        float wt = __ldg(&d_nrm[k]);
        float4 v = __ldg(&hb[src * 64 + 32 + lane]);
        acc.x = fmaf(wt, v.x, acc.x); acc.y = fmaf(wt, v.y, acc.y);
        acc.z = fmaf(wt, v.z, acc.z); acc.w = fmaf(wt, v.w, acc.w);
    }
    ((float4*)d_cat)[w * 64 + lane] = acc;
}

// ---------------- SGEMM (R3-identical inner loop; B pre-scaled):
//   out = ReLU( [s_raw|act] @ Wscl + wsum[m]*u + b2 )
__global__ void __launch_bounds__(256) k_sgemm(int Nn, int toCat) {
    __shared__ float As[2][8][128];
    __shared__ float Bs[2][8][128];
    const float* A = d_cat;
    const float* B = d_Wscl;
    int tid = threadIdx.x;
    int bm = blockIdx.x * 128, bn = blockIdx.y * 128;
    int tx = tid & 15, ty = tid >> 4;

    float acc[8][8];
#pragma unroll
    for (int i = 0; i < 8; i++)
#pragma unroll
        for (int j = 0; j < 8; j++) acc[i][j] = 0.f;

    int arow = bm + (tid >> 1);
    int akq = (tid & 1) * 4;
    int bkr = tid >> 5, bnq = (tid & 31) * 4;

    float4 av, bv;
    av = (arow < NN) ? *(const float4*)(A + arow * 256 + akq) : make_float4(0.f, 0.f, 0.f, 0.f);
    bv = *(const float4*)(B + bkr * Nn + bn + bnq);
    As[0][akq + 0][tid >> 1] = av.x;
    As[0][akq + 1][tid >> 1] = av.y;
    As[0][akq + 2][tid >> 1] = av.z;
    As[0][akq + 3][tid >> 1] = av.w;
    *(float4*)&Bs[0][bkr][bnq] = bv;
    __syncthreads();

    int buf = 0;
    for (int ks = 0; ks < 32; ks++) {
        int k0n = (ks + 1) * 8;
        if (ks < 31) {
            av = (arow < NN) ? *(const float4*)(A + arow * 256 + k0n + akq)
                             : make_float4(0.f, 0.f, 0.f, 0.f);
            bv = *(const float4*)(B + (k0n + bkr) * Nn + bn + bnq);
        }
#pragma unroll
        for (int k = 0; k < 8; k++) {
            float a[8], b[8];
            *(float4*)&a[0] = *(const float4*)&As[buf][k][ty * 4];
            *(float4*)&a[4] = *(const float4*)&As[buf][k][64 + ty * 4];
            *(float4*)&b[0] = *(const float4*)&Bs[buf][k][tx * 4];
            *(float4*)&b[4] = *(const float4*)&Bs[buf][k][64 + tx * 4];
#pragma unroll
            for (int i = 0; i < 8; i++)
#pragma unroll
                for (int j = 0; j < 8; j++) acc[i][j] = fmaf(a[i], b[j], acc[i][j]);
        }
        if (ks < 31) {
            int nb = buf ^ 1;
            As[nb][akq + 0][tid >> 1] = av.x;
            As[nb][akq + 1][tid >> 1] = av.y;
            As[nb][akq + 2][tid >> 1] = av.z;
            As[nb][akq + 3][tid >> 1] = av.w;
            *(float4*)&Bs[nb][bkr][bnq] = bv;
            __syncthreads();
            buf = nb;
        }
    }

#pragma unroll
    for (int i = 0; i < 8; i++) {
        int m = bm + ((i < 4) ? (ty * 4 + i) : (64 + ty * 4 + i - 4));
        if (m < NN) {
            float wsm = d_wsum[m];
#pragma unroll
            for (int j = 0; j < 8; j++) {
                int n = bn + ((j < 4) ? (tx * 4 + j) : (64 + tx * 4 + j - 4));
                float v = acc[i][j] + d_b2[n] + wsm * d_u[n];
                v = (v > 0.f) ? v : 0.f;
                if (toCat) d_cat[m * 256 + 128 + n] = v;
                else       d_act[m * Nn + n] = v;
            }
        }
    }
}

// ---------------- column stats: sum, sumsq over rows (pointer resolved device-side) ----------------
__global__ void k_stats(int which, int F) {
    const float* base = which ? (const float*)d_act : (const float*)(d_cat + 128);
    int f = threadIdx.x;
    float s = 0.f, s2 = 0.f;
    for (int n = blockIdx.x; n < NN; n += gridDim.x) {
        float v = base[n * 256 + f];
        s += v;
        s2 += v * v;
    }
    atomicAdd(&d_stats[f], s);
    atomicAdd(&d_stats[256 + f], s2);
}

// ---------------- global add pool: out[g,f] = scl[f]*sum(act6) + cnt_g*shl[f] ----------------
__global__ void k_pool(float* __restrict__ out) {
    int g = blockIdx.x, f = threadIdx.x;
    int n0 = d_goff[g], n1 = d_goff[g + 1];
    float s = 0.f;
    for (int n = n0; n < n1; n++) s += d_act[n * 256 + f];
    out[g * 256 + f] = d_scl[f] * s + (float)(n1 - n0) * d_shl[f];
}

// ---------------- launch ----------------
extern "C" void kernel_launch(void* const* d_in, const int* in_sizes, int n_in,
                              void* d_out, int out_size) {
    const float* x   = (const float*)d_in[0];
    const void*  ei  = d_in[1];
    const void*  bat = d_in[2];
    const float* Wi  = (const float*)d_in[3];
    const float* Wr  = (const float*)d_in[4];
    const float* b   = (const float*)d_in[5];
    const float* g   = (const float*)d_in[6];
    const float* be  = (const float*)d_in[7];
    const float* Wi6 = (const float*)d_in[8];
    const float* Wr6 = (const float*)d_in[9];
    const float* b6  = (const float*)d_in[10];
    const float* g6  = (const float*)d_in[11];
    const float* be6 = (const float*)d_in[12];
    float* out = (float*)d_out;

    // launches 0..4 are the dependency chain; launch 5 (ncu capture target) = first k_spmm
    k_detect<<<1, 256>>>((const unsigned int*)ei);                       // 0
    k_extract_copy<<<(NN * 32 + 255) / 256, 256>>>(ei, x);               // 1
    k_count<<<(EE + 255) / 256, 256>>>();                                // 2
    k_scan<<<1, 1024>>>();                                               // 3
    k_fill<<<(EE + 255) / 256, 256>>>();                                 // 4
    k_spmm<<<(NN + 7) / 8, 256>>>();                                     // 5  <- profiled
    k_wsum<<<(NN + 7) / 8, 256>>>();
    k_wcat<<<(5 * 32768 + 65536 + 255) / 256, 256>>>(Wi, Wr, Wi6, Wr6);
    k_goff<<<(NN + 255) / 256, 256>>>(bat);

    const int mblocks = (NN + 127) / 128;
    for (int l = 0; l < 5; l++) {
        if (l > 0) k_spmm<<<(NN + 7) / 8, 256>>>();
        if (l == 0) k_initbn<<<1, 128>>>();
        else        k_mkbn<<<1, 256>>>(g + (l - 1) * 128, be + (l - 1) * 128, 128);
        k_scaleB<<<128, 256>>>(l * 32768, 128);
        k_mkub<<<1, 256>>>(Wi + l * 16384, Wr + l * 16384, b + l * 128, 128);
        k_sgemm<<<dim3(mblocks, 1), 256>>>(128, 1);
        k_stats<<<512, 128>>>(0, 128);
    }
    // layer 6 (F_OUT = 256)
    k_spmm<<<(NN + 7) / 8, 256>>>();
    k_mkbn<<<1, 256>>>(g + 4 * 128, be + 4 * 128, 128);
    k_scaleB<<<256, 256>>>(5 * 32768, 256);
    k_mkub<<<1, 256>>>(Wi6, Wr6, b6, 256);
    k_sgemm<<<dim3(mblocks, 2), 256>>>(256, 0);
    k_stats<<<512, 256>>>(1, 256);

    k_mkbn<<<1, 256>>>(g6, be6, 256);
    k_pool<<<GG, 256>>>(out);
}

// round 8
// speedup vs baseline: 2.2261x; 1.1431x over previous
#include <cuda_runtime.h>

#define NN 100000
#define EE 1600000
#define GG 2000
#define BN_EPS 1e-5f
#define NB 391   // ceil(NN/256)

// ---------------- scratch (static device globals; no runtime alloc) ----------------
__device__ __align__(16) float d_cat[NN * 256];   // cols [0:128)=s_raw=A@act, cols [128:256)=act (raw)
__device__ __align__(16) float d_act[NN * 256];   // layer-6 raw output (pre-BN), for pooling
__device__ int   d_flag;            // 1 = inputs are int64, 0 = int32
__device__ int   d_row[EE];
__device__ int   d_colv[EE];
__device__ int   d_deg[NN];
__device__ float d_dinv[NN];
__device__ int   d_off[NN + 1];
__device__ int   d_cur[NN];
__device__ int   d_bsum[512];
__device__ int   d_src[EE];
__device__ float d_nrm[EE];
__device__ float d_wsum[NN];
__device__ int   d_goff[GG + 1];
__device__ __align__(16) float d_Wcat[5 * 256 * 128 + 256 * 256];  // [Wi;Wr] per layer, [256,F] row-major
__device__ __align__(16) float d_Wscl[256 * 256];  // current layer's diag(scl) * Wcat
__device__ float d_stats[512];      // [0:256)=sum, [256:512)=sumsq of current raw act
__device__ float d_scl[256];        // BN scale of previous layer (per input feature)
__device__ float d_shl[256];        // BN shift of previous layer
__device__ float d_u[256];          // u[o] = shl @ Wi_l
__device__ float d_b2[256];         // b2[o] = b_l + shl @ Wr_l

// ---------------- dtype detection: int64 buffers have zero hi-words ----------------
__global__ void k_detect(const unsigned int* __restrict__ buf) {
    __shared__ int any;
    if (threadIdx.x == 0) any = 0;
    __syncthreads();
    const int S = 2 * EE / 2048;
    for (int k = threadIdx.x; k < 1024; k += blockDim.x) {
        unsigned int w = buf[2 * (k * S) + 1];
        if (w != 0u) atomicOr(&any, 1);
    }
    __syncthreads();
    if (threadIdx.x == 0) d_flag = (any == 0) ? 1 : 0;
}

// extract edges + zero deg + copy x into d_cat h-half (one kernel, 3.2M threads)
__global__ void k_extract_copy(const void* __restrict__ eiv, const float* __restrict__ x) {
    int i = blockIdx.x * blockDim.x + threadIdx.x;
    if (i < NN * 32) {
        int n = i >> 5, c = i & 31;
        ((float4*)d_cat)[n * 64 + 32 + c] = ((const float4*)x)[i];
    }
    if (i < NN) d_deg[i] = 0;
    if (i < EE) {
        int r, c;
        if (d_flag) {
            const long long* p = (const long long*)eiv;
            r = (int)p[i]; c = (int)p[EE + i];
        } else {
            const int* p = (const int*)eiv;
            r = p[i]; c = p[EE + i];
        }
        d_row[i] = r; d_colv[i] = c;
    }
}

__global__ void k_count() {
    int e = blockIdx.x * blockDim.x + threadIdx.x;
    if (e < EE) atomicAdd(&d_deg[d_colv[e]], 1);
}

// ---------------- grid-wide exclusive scan of d_deg (3 phases) ----------------
__global__ void k_scan1() {   // NB blocks: per-block degree sums
    __shared__ int sh[256];
    int i = blockIdx.x * 256 + threadIdx.x;
    sh[threadIdx.x] = (i < NN) ? d_deg[i] : 0;
    __syncthreads();
#pragma unroll
    for (int o = 128; o > 0; o >>= 1) {
        if (threadIdx.x < o) sh[threadIdx.x] += sh[threadIdx.x + o];
        __syncthreads();
    }
    if (threadIdx.x == 0) d_bsum[blockIdx.x] = sh[0];
}

__global__ void k_scan2() {   // 1 block, 512 threads: exclusive scan of block sums
    __shared__ int sh[512];
    int t = threadIdx.x;
    int v = (t < NB) ? d_bsum[t] : 0;
    sh[t] = v;
    __syncthreads();
    for (int o = 1; o < 512; o <<= 1) {
        int u = (t >= o) ? sh[t - o] : 0;
        __syncthreads();
        sh[t] += u;
        __syncthreads();
    }
    if (t < NB) d_bsum[t] = sh[t] - v;   // exclusive
}

__global__ void k_scan3() {   // NB blocks: in-block scan + base; emit off/cur/dinv
    __shared__ int sh[256];
    int i = blockIdx.x * 256 + threadIdx.x;
    int d = (i < NN) ? d_deg[i] : 0;
    sh[threadIdx.x] = d;
    __syncthreads();
    for (int o = 1; o < 256; o <<= 1) {
        int u = (threadIdx.x >= o) ? sh[threadIdx.x - o] : 0;
        __syncthreads();
        sh[threadIdx.x] += u;
        __syncthreads();
    }
    if (i < NN) {
        int run = d_bsum[blockIdx.x] + sh[threadIdx.x] - d;   // exclusive prefix
        d_off[i] = run;
        d_cur[i] = run;
        d_dinv[i] = (d > 0) ? rsqrtf((float)d) : 0.0f;
        if (i == NN - 1) d_off[NN] = EE;
    }
}

__global__ void k_fill() {
    int e = blockIdx.x * blockDim.x + threadIdx.x;
    if (e < EE) {
        int r = d_row[e];
        int c = d_colv[e];
        int p = atomicAdd(&d_cur[c], 1);
        d_src[p] = r;
        d_nrm[p] = d_dinv[r] * d_dinv[c];
    }
}

__global__ void k_wsum() {   // warp per node: wsum[i] = sum of edge norms into i
    int w = (blockIdx.x * blockDim.x + threadIdx.x) >> 5;
    int lane = threadIdx.x & 31;
    if (w >= NN) return;
    int s0 = d_off[w], s1 = d_off[w + 1];
    float s = 0.f;
    for (int k = s0 + lane; k < s1; k += 32) s += d_nrm[k];
#pragma unroll
    for (int o = 16; o > 0; o >>= 1) s += __shfl_xor_sync(0xffffffffu, s, o);
    if (lane == 0) d_wsum[w] = s;
}

__global__ void k_wcat(const float* __restrict__ Wi, const float* __restrict__ Wr,
                       const float* __restrict__ Wi6, const float* __restrict__ Wr6) {
    int i = blockIdx.x * blockDim.x + threadIdx.x;
    const int L5 = 5 * 256 * 128;
    if (i < L5) {
        int l = i >> 15;
        int rem = i & 32767;
        int k = rem >> 7, f = rem & 127;
        d_Wcat[i] = (k < 128) ? Wi[(l << 14) + (k << 7) + f]
                              : Wr[(l << 14) + ((k - 128) << 7) + f];
    } else if (i < L5 + 65536) {
        int j = i - L5;
        int k = j >> 8, f = j & 255;
        d_Wcat[i] = (k < 128) ? Wi6[(k << 8) + f] : Wr6[((k - 128) << 8) + f];
    }
}

__global__ void k_goff(const void* __restrict__ bv) {   // batch sorted; reads raw input
    int n = blockIdx.x * blockDim.x + threadIdx.x;
    if (n >= NN) return;
    int bn, bp;
    if (d_flag) {
        const long long* p = (const long long*)bv;
        bn = (int)p[n]; bp = (n == 0) ? -1 : (int)p[n - 1];
    } else {
        const int* p = (const int*)bv;
        bn = p[n]; bp = (n == 0) ? -1 : p[n - 1];
    }
    for (int id = bp + 1; id <= bn; id++) d_goff[id] = n;
    if (n == NN - 1)
        for (int id = bn + 1; id <= GG; id++) d_goff[id] = NN;
}

// ---------------- BN fold: compute scl/shl from stats; init u/b2/stats ----------------
__global__ void k_bnfold(const float* __restrict__ gamma, const float* __restrict__ beta,
                         const float* __restrict__ b, int Nn, int ident) {
    int f = threadIdx.x;   // 256 threads
    if (f < 128) {
        float sc, sh;
        if (ident) { sc = 1.f; sh = 0.f; }
        else {
            float mu = d_stats[f] * (1.f / NN);
            float var = d_stats[256 + f] * (1.f / NN) - mu * mu;
            sc = gamma[f] * rsqrtf(var + BN_EPS);
            sh = beta[f] - mu * sc;
        }
        d_scl[f] = sc;
        d_shl[f] = sh;
    }
    d_stats[f] = 0.f;
    d_stats[256 + f] = 0.f;
    if (f < Nn) { d_u[f] = 0.f; d_b2[f] = b[f]; }
}

// B_scaled[k][n] = scl[k & 127] * Wcat[k][n]
__global__ void k_scaleB(int wofs, int Nn) {
    int i = blockIdx.x * blockDim.x + threadIdx.x;
    if (i < 256 * Nn) d_Wscl[i] = d_scl[(i / Nn) & 127] * d_Wcat[wofs + i];
}

// u += shl@Wi, b2 += shl@Wr over this block's 8 k-values (16 blocks)
__global__ void k_mkub_par(const float* __restrict__ Wi, const float* __restrict__ Wr, int Nn) {
    int f = threadIdx.x;
    if (f >= Nn) return;
    int k0 = blockIdx.x * 8;
    float u = 0.f, bb = 0.f;
#pragma unroll
    for (int k = k0; k < k0 + 8; k++) {
        float sh = d_shl[k];
        u  = fmaf(sh, Wi[k * Nn + f], u);
        bb = fmaf(sh, Wr[k * Nn + f], bb);
    }
    atomicAdd(&d_u[f], u);
    atomicAdd(&d_b2[f], bb);
}

// ---------------- SpMM: s_raw[i,:] = sum_{e: col=i} norm_e * act[row_e,:]  (warp per node) ----------------
__global__ void k_spmm() {
    int w = (blockIdx.x * blockDim.x + threadIdx.x) >> 5;
    int lane = threadIdx.x & 31;
    if (w >= NN) return;
    int s0 = d_off[w], s1 = d_off[w + 1];
    float4 acc = make_float4(0.f, 0.f, 0.f, 0.f);
    const float4* hb = (const float4*)d_cat;
    int k = s0;
    for (; k + 1 < s1; k += 2) {
        int src0 = __ldg(&d_src[k]);
        int src1 = __ldg(&d_src[k + 1]);
        float w0 = __ldg(&d_nrm[k]);
        float w1 = __ldg(&d_nrm[k + 1]);
        float4 v0 = __ldg(&hb[src0 * 64 + 32 + lane]);
        float4 v1 = __ldg(&hb[src1 * 64 + 32 + lane]);
        acc.x = fmaf(w0, v0.x, acc.x); acc.y = fmaf(w0, v0.y, acc.y);
        acc.z = fmaf(w0, v0.z, acc.z); acc.w = fmaf(w0, v0.w, acc.w);
        acc.x = fmaf(w1, v1.x, acc.x); acc.y = fmaf(w1, v1.y, acc.y);
        acc.z = fmaf(w1, v1.z, acc.z); acc.w = fmaf(w1, v1.w, acc.w);
    }
    if (k < s1) {
        int src = __ldg(&d_src[k]);
        float wt = __ldg(&d_nrm[k]);
        float4 v = __ldg(&hb[src * 64 + 32 + lane]);
        acc.x = fmaf(wt, v.x, acc.x); acc.y = fmaf(wt, v.y, acc.y);
        acc.z = fmaf(wt, v.z, acc.z); acc.w = fmaf(wt, v.w, acc.w);
    }
    ((float4*)d_cat)[w * 64 + lane] = acc;
}

// ---------------- SGEMM (R3-identical inner loop; B pre-scaled):
//   out = ReLU( [s_raw|act] @ Wscl + wsum[m]*u + b2 )
__global__ void __launch_bounds__(256) k_sgemm(int Nn, int toCat) {
    __shared__ float As[2][8][128];
    __shared__ float Bs[2][8][128];
    const float* A = d_cat;
    const float* B = d_Wscl;
    int tid = threadIdx.x;
    int bm = blockIdx.x * 128, bn = blockIdx.y * 128;
    int tx = tid & 15, ty = tid >> 4;

    float acc[8][8];
#pragma unroll
    for (int i = 0; i < 8; i++)
#pragma unroll
        for (int j = 0; j < 8; j++) acc[i][j] = 0.f;

    int arow = bm + (tid >> 1);
    int akq = (tid & 1) * 4;
    int bkr = tid >> 5, bnq = (tid & 31) * 4;

    float4 av, bv;
    av = (arow < NN) ? *(const float4*)(A + arow * 256 + akq) : make_float4(0.f, 0.f, 0.f, 0.f);
    bv = *(const float4*)(B + bkr * Nn + bn + bnq);
    As[0][akq + 0][tid >> 1] = av.x;
    As[0][akq + 1][tid >> 1] = av.y;
    As[0][akq + 2][tid >> 1] = av.z;
    As[0][akq + 3][tid >> 1] = av.w;
    *(float4*)&Bs[0][bkr][bnq] = bv;
    __syncthreads();

    int buf = 0;
    for (int ks = 0; ks < 32; ks++) {
        int k0n = (ks + 1) * 8;
        if (ks < 31) {
            av = (arow < NN) ? *(const float4*)(A + arow * 256 + k0n + akq)
                             : make_float4(0.f, 0.f, 0.f, 0.f);
            bv = *(const float4*)(B + (k0n + bkr) * Nn + bn + bnq);
        }
#pragma unroll
        for (int k = 0; k < 8; k++) {
            float a[8], b[8];
            *(float4*)&a[0] = *(const float4*)&As[buf][k][ty * 4];
            *(float4*)&a[4] = *(const float4*)&As[buf][k][64 + ty * 4];
            *(float4*)&b[0] = *(const float4*)&Bs[buf][k][tx * 4];
            *(float4*)&b[4] = *(const float4*)&Bs[buf][k][64 + tx * 4];
#pragma unroll
            for (int i = 0; i < 8; i++)
#pragma unroll
                for (int j = 0; j < 8; j++) acc[i][j] = fmaf(a[i], b[j], acc[i][j]);
        }
        if (ks < 31) {
            int nb = buf ^ 1;
            As[nb][akq + 0][tid >> 1] = av.x;
            As[nb][akq + 1][tid >> 1] = av.y;
            As[nb][akq + 2][tid >> 1] = av.z;
            As[nb][akq + 3][tid >> 1] = av.w;
            *(float4*)&Bs[nb][bkr][bnq] = bv;
            __syncthreads();
            buf = nb;
        }
    }

#pragma unroll
    for (int i = 0; i < 8; i++) {
        int m = bm + ((i < 4) ? (ty * 4 + i) : (64 + ty * 4 + i - 4));
        if (m < NN) {
            float wsm = d_wsum[m];
#pragma unroll
            for (int j = 0; j < 8; j++) {
                int n = bn + ((j < 4) ? (tx * 4 + j) : (64 + tx * 4 + j - 4));
                float v = acc[i][j] + d_b2[n] + wsm * d_u[n];
                v = (v > 0.f) ? v : 0.f;
                if (toCat) d_cat[m * 256 + 128 + n] = v;
                else       d_act[m * Nn + n] = v;
            }
        }
    }
}

// ---------------- column stats: sum, sumsq over rows (pointer resolved device-side) ----------------
__global__ void k_stats(int which, int F) {
    const float* base = which ? (const float*)d_act : (const float*)(d_cat + 128);
    int f = threadIdx.x;
    float s = 0.f, s2 = 0.f;
    for (int n = blockIdx.x; n < NN; n += gridDim.x) {
        float v = base[n * 256 + f];
        s += v;
        s2 += v * v;
    }
    atomicAdd(&d_stats[f], s);
    atomicAdd(&d_stats[256 + f], s2);
}

// ---------------- final BN coefs for pool ----------------
__global__ void k_mkbn(const float* __restrict__ gamma, const float* __restrict__ beta, int F) {
    int f = threadIdx.x;
    if (f >= F) return;
    float mu = d_stats[f] * (1.f / NN);
    float var = d_stats[256 + f] * (1.f / NN) - mu * mu;
    float sc = gamma[f] * rsqrtf(var + BN_EPS);
    d_scl[f] = sc;
    d_shl[f] = beta[f] - mu * sc;
}

// ---------------- global add pool: out[g,f] = scl[f]*sum(act6) + cnt_g*shl[f] ----------------
__global__ void k_pool(float* __restrict__ out) {
    int g = blockIdx.x, f = threadIdx.x;
    int n0 = d_goff[g], n1 = d_goff[g + 1];
    float s = 0.f;
    for (int n = n0; n < n1; n++) s += d_act[n * 256 + f];
    out[g * 256 + f] = d_scl[f] * s + (float)(n1 - n0) * d_shl[f];
}

// ---------------- launch ----------------
extern "C" void kernel_launch(void* const* d_in, const int* in_sizes, int n_in,
                              void* d_out, int out_size) {
    const float* x   = (const float*)d_in[0];
    const void*  ei  = d_in[1];
    const void*  bat = d_in[2];
    const float* Wi  = (const float*)d_in[3];
    const float* Wr  = (const float*)d_in[4];
    const float* b   = (const float*)d_in[5];
    const float* g   = (const float*)d_in[6];
    const float* be  = (const float*)d_in[7];
    const float* Wi6 = (const float*)d_in[8];
    const float* Wr6 = (const float*)d_in[9];
    const float* b6  = (const float*)d_in[10];
    const float* g6  = (const float*)d_in[11];
    const float* be6 = (const float*)d_in[12];
    float* out = (float*)d_out;

    k_detect<<<1, 256>>>((const unsigned int*)ei);
    k_extract_copy<<<(NN * 32 + 255) / 256, 256>>>(ei, x);
    k_count<<<(EE + 255) / 256, 256>>>();
    k_scan1<<<NB, 256>>>();
    k_scan2<<<1, 512>>>();
    k_scan3<<<NB, 256>>>();
    k_fill<<<(EE + 255) / 256, 256>>>();
    k_wsum<<<(NN + 7) / 8, 256>>>();
    k_wcat<<<(5 * 32768 + 65536 + 255) / 256, 256>>>(Wi, Wr, Wi6, Wr6);
    k_goff<<<(NN + 255) / 256, 256>>>(bat);

    const int mblocks = (NN + 127) / 128;
    for (int l = 0; l < 5; l++) {
        k_spmm<<<(NN + 7) / 8, 256>>>();
        k_bnfold<<<1, 256>>>(g + (l - 1) * 128, be + (l - 1) * 128, b + l * 128, 128, l == 0);
        k_scaleB<<<128, 256>>>(l * 32768, 128);
        k_mkub_par<<<16, 128>>>(Wi + l * 16384, Wr + l * 16384, 128);
        k_sgemm<<<dim3(mblocks, 1), 256>>>(128, 1);
        k_stats<<<512, 128>>>(0, 128);
    }
    // layer 6 (F_OUT = 256)
    k_spmm<<<(NN + 7) / 8, 256>>>();
    k_bnfold<<<1, 256>>>(g + 4 * 128, be + 4 * 128, b6, 256, 0);
    k_scaleB<<<256, 256>>>(5 * 32768, 256);
    k_mkub_par<<<16, 256>>>(Wi6, Wr6, 256);
    k_sgemm<<<dim3(mblocks, 2), 256>>>(256, 0);
    k_stats<<<512, 256>>>(1, 256);

    k_mkbn<<<1, 256>>>(g6, be6, 256);
    k_pool<<<GG, 256>>>(out);
}

// round 11
// speedup vs baseline: 3.2226x; 1.4477x over previous
#include <cuda_runtime.h>
#include <cuda_bf16.h>
#include <cstdint>

#define NN 100000
#define EE 1600000
#define GG 2000
#define BN_EPS 1e-5f
#define NB 391   // ceil(NN/256)

// ---------------- scratch (static device globals; no runtime alloc) ----------------
__device__ __align__(16) float d_cat[NN * 256];   // cols [0:128)=s_raw=A@act, cols [128:256)=act (raw)
__device__ __align__(16) float d_act[NN * 256];   // layer-6 raw output (pre-BN), for pooling
__device__ int   d_flag;
__device__ int   d_row[EE];
__device__ int   d_colv[EE];
__device__ int   d_deg[NN];
__device__ float d_dinv[NN];
__device__ int   d_off[NN + 1];
__device__ int   d_cur[NN];
__device__ int   d_bsum[512];
__device__ int   d_src[EE];
__device__ float d_nrm[EE];
__device__ float d_wsum[NN];
__device__ int   d_goff[GG + 1];
__device__ __align__(16) float d_Wcat[5 * 256 * 128 + 256 * 256];  // [Wi;Wr] per layer, [256,F] row-major
__device__ __align__(16) unsigned int d_Bhi[256 * 128];  // B hi: [n][kp] bf16x2, row = 128 uints
__device__ __align__(16) unsigned int d_Blo[256 * 128];  // B lo
__device__ float d_stats[512];
__device__ float d_scl[256];
__device__ float d_shl[256];
__device__ float d_u[256];
__device__ float d_b2[256];

// ---------------- mma.sync helper (sm_80+ portable HMMA) ----------------
__device__ __forceinline__ void mma16816(float* c, const uint32_t* a, uint32_t b0, uint32_t b1) {
    asm volatile(
        "mma.sync.aligned.m16n8k16.row.col.f32.bf16.bf16.f32 "
        "{%0,%1,%2,%3}, {%4,%5,%6,%7}, {%8,%9}, {%0,%1,%2,%3};"
        : "+f"(c[0]), "+f"(c[1]), "+f"(c[2]), "+f"(c[3])
        : "r"(a[0]), "r"(a[1]), "r"(a[2]), "r"(a[3]), "r"(b0), "r"(b1));
}

// ---------------- dtype detection ----------------
__global__ void k_detect(const unsigned int* __restrict__ buf) {
    __shared__ int any;
    if (threadIdx.x == 0) any = 0;
    __syncthreads();
    const int S = 2 * EE / 2048;
    for (int k = threadIdx.x; k < 1024; k += blockDim.x) {
        unsigned int w = buf[2 * (k * S) + 1];
        if (w != 0u) atomicOr(&any, 1);
    }
    __syncthreads();
    if (threadIdx.x == 0) d_flag = (any == 0) ? 1 : 0;
}

__global__ void k_extract_copy(const void* __restrict__ eiv, const float* __restrict__ x) {
    int i = blockIdx.x * blockDim.x + threadIdx.x;
    if (i < NN * 32) {
        int n = i >> 5, c = i & 31;
        ((float4*)d_cat)[n * 64 + 32 + c] = ((const float4*)x)[i];
    }
    if (i < NN) d_deg[i] = 0;
    if (i < EE) {
        int r, c;
        if (d_flag) {
            const long long* p = (const long long*)eiv;
            r = (int)p[i]; c = (int)p[EE + i];
        } else {
            const int* p = (const int*)eiv;
            r = p[i]; c = p[EE + i];
        }
        d_row[i] = r; d_colv[i] = c;
    }
}

__global__ void k_count() {
    int e = blockIdx.x * blockDim.x + threadIdx.x;
    if (e < EE) atomicAdd(&d_deg[d_colv[e]], 1);
}

// ---------------- grid-wide exclusive scan (3 phases) ----------------
__global__ void k_scan1() {
    __shared__ int sh[256];
    int i = blockIdx.x * 256 + threadIdx.x;
    sh[threadIdx.x] = (i < NN) ? d_deg[i] : 0;
    __syncthreads();
#pragma unroll
    for (int o = 128; o > 0; o >>= 1) {
        if (threadIdx.x < o) sh[threadIdx.x] += sh[threadIdx.x + o];
        __syncthreads();
    }
    if (threadIdx.x == 0) d_bsum[blockIdx.x] = sh[0];
}

__global__ void k_scan2() {
    __shared__ int sh[512];
    int t = threadIdx.x;
    int v = (t < NB) ? d_bsum[t] : 0;
    sh[t] = v;
    __syncthreads();
    for (int o = 1; o < 512; o <<= 1) {
        int u = (t >= o) ? sh[t - o] : 0;
        __syncthreads();
        sh[t] += u;
        __syncthreads();
    }
    if (t < NB) d_bsum[t] = sh[t] - v;
}

__global__ void k_scan3() {
    __shared__ int sh[256];
    int i = blockIdx.x * 256 + threadIdx.x;
    int d = (i < NN) ? d_deg[i] : 0;
    sh[threadIdx.x] = d;
    __syncthreads();
    for (int o = 1; o < 256; o <<= 1) {
        int u = (threadIdx.x >= o) ? sh[threadIdx.x - o] : 0;
        __syncthreads();
        sh[threadIdx.x] += u;
        __syncthreads();
    }
    if (i < NN) {
        int run = d_bsum[blockIdx.x] + sh[threadIdx.x] - d;
        d_off[i] = run;
        d_cur[i] = run;
        d_dinv[i] = (d > 0) ? rsqrtf((float)d) : 0.0f;
        if (i == NN - 1) d_off[NN] = EE;
    }
}

__global__ void k_fill() {
    int e = blockIdx.x * blockDim.x + threadIdx.x;
    if (e < EE) {
        int r = d_row[e];
        int c = d_colv[e];
        int p = atomicAdd(&d_cur[c], 1);
        d_src[p] = r;
        d_nrm[p] = d_dinv[r] * d_dinv[c];
    }
}

__global__ void k_wsum() {
    int w = (blockIdx.x * blockDim.x + threadIdx.x) >> 5;
    int lane = threadIdx.x & 31;
    if (w >= NN) return;
    int s0 = d_off[w], s1 = d_off[w + 1];
    float s = 0.f;
    for (int k = s0 + lane; k < s1; k += 32) s += d_nrm[k];
#pragma unroll
    for (int o = 16; o > 0; o >>= 1) s += __shfl_xor_sync(0xffffffffu, s, o);
    if (lane == 0) d_wsum[w] = s;
}

__global__ void k_wcat(const float* __restrict__ Wi, const float* __restrict__ Wr,
                       const float* __restrict__ Wi6, const float* __restrict__ Wr6) {
    int i = blockIdx.x * blockDim.x + threadIdx.x;
    const int L5 = 5 * 256 * 128;
    if (i < L5) {
        int l = i >> 15;
        int rem = i & 32767;
        int k = rem >> 7, f = rem & 127;
        d_Wcat[i] = (k < 128) ? Wi[(l << 14) + (k << 7) + f]
                              : Wr[(l << 14) + ((k - 128) << 7) + f];
    } else if (i < L5 + 65536) {
        int j = i - L5;
        int k = j >> 8, f = j & 255;
        d_Wcat[i] = (k < 128) ? Wi6[(k << 8) + f] : Wr6[((k - 128) << 8) + f];
    }
}

__global__ void k_goff(const void* __restrict__ bv) {
    int n = blockIdx.x * blockDim.x + threadIdx.x;
    if (n >= NN) return;
    int bn, bp;
    if (d_flag) {
        const long long* p = (const long long*)bv;
        bn = (int)p[n]; bp = (n == 0) ? -1 : (int)p[n - 1];
    } else {
        const int* p = (const int*)bv;
        bn = p[n]; bp = (n == 0) ? -1 : p[n - 1];
    }
    for (int id = bp + 1; id <= bn; id++) d_goff[id] = n;
    if (n == NN - 1)
        for (int id = bn + 1; id <= GG; id++) d_goff[id] = NN;
}

// ---------------- BN fold: scl/shl from stats; init u/b2/stats ----------------
__global__ void k_bnfold(const float* __restrict__ gamma, const float* __restrict__ beta,
                         const float* __restrict__ b, int Nn, int ident) {
    int f = threadIdx.x;   // 256
    if (f < 128) {
        float sc, sh;
        if (ident) { sc = 1.f; sh = 0.f; }
        else {
            float mu = d_stats[f] * (1.f / NN);
            float var = d_stats[256 + f] * (1.f / NN) - mu * mu;
            sc = gamma[f] * rsqrtf(var + BN_EPS);
            sh = beta[f] - mu * sc;
        }
        d_scl[f] = sc;
        d_shl[f] = sh;
    }
    d_stats[f] = 0.f;
    d_stats[256 + f] = 0.f;
    if (f < Nn) { d_u[f] = 0.f; d_b2[f] = b[f]; }
}

// B split: w = scl[k&127]*Wcat[k][n]; hi/lo bf16 into [n][k] K-major global
__global__ void k_scaleBsplit(int wofs, int Nn) {
    int i = blockIdx.x * blockDim.x + threadIdx.x;
    if (i >= 256 * Nn) return;
    int k = i & 255, n = i >> 8;
    float w = d_scl[k & 127] * d_Wcat[wofs + k * Nn + n];
    __nv_bfloat16 h = __float2bfloat16(w);
    __nv_bfloat16 l = __float2bfloat16(w - __bfloat162float(h));
    ((__nv_bfloat16*)d_Bhi)[n * 256 + k] = h;
    ((__nv_bfloat16*)d_Blo)[n * 256 + k] = l;
}

__global__ void k_mkub_par(const float* __restrict__ Wi, const float* __restrict__ Wr, int Nn) {
    int f = threadIdx.x;
    if (f >= Nn) return;
    int k0 = blockIdx.x * 8;
    float u = 0.f, bb = 0.f;
#pragma unroll
    for (int k = k0; k < k0 + 8; k++) {
        float sh = d_shl[k];
        u  = fmaf(sh, Wi[k * Nn + f], u);
        bb = fmaf(sh, Wr[k * Nn + f], bb);
    }
    atomicAdd(&d_u[f], u);
    atomicAdd(&d_b2[f], bb);
}

// ---------------- SpMM (unchanged, proven) ----------------
__global__ void k_spmm() {
    int w = (blockIdx.x * blockDim.x + threadIdx.x) >> 5;
    int lane = threadIdx.x & 31;
    if (w >= NN) return;
    int s0 = d_off[w], s1 = d_off[w + 1];
    float4 acc = make_float4(0.f, 0.f, 0.f, 0.f);
    const float4* hb = (const float4*)d_cat;
    int k = s0;
    for (; k + 1 < s1; k += 2) {
        int src0 = __ldg(&d_src[k]);
        int src1 = __ldg(&d_src[k + 1]);
        float w0 = __ldg(&d_nrm[k]);
        float w1 = __ldg(&d_nrm[k + 1]);
        float4 v0 = __ldg(&hb[src0 * 64 + 32 + lane]);
        float4 v1 = __ldg(&hb[src1 * 64 + 32 + lane]);
        acc.x = fmaf(w0, v0.x, acc.x); acc.y = fmaf(w0, v0.y, acc.y);
        acc.z = fmaf(w0, v0.z, acc.z); acc.w = fmaf(w0, v0.w, acc.w);
        acc.x = fmaf(w1, v1.x, acc.x); acc.y = fmaf(w1, v1.y, acc.y);
        acc.z = fmaf(w1, v1.z, acc.z); acc.w = fmaf(w1, v1.w, acc.w);
    }
    if (k < s1) {
        int src = __ldg(&d_src[k]);
        float wt = __ldg(&d_nrm[k]);
        float4 v = __ldg(&hb[src * 64 + 32 + lane]);
        acc.x = fmaf(wt, v.x, acc.x); acc.y = fmaf(wt, v.y, acc.y);
        acc.z = fmaf(wt, v.z, acc.z); acc.w = fmaf(wt, v.w, acc.w);
    }
    ((float4*)d_cat)[w * 64 + lane] = acc;
}

// ---------------- HMMA GEMM (mma.sync bf16 hi/lo split):
//   D = [s_raw|act] @ Bsplit ; out = ReLU(D + wsum*u + b2)
//   Block 128x128, 8 warps (4Mx2N), warp tile 32x64, K in 16 chunks of 16.
__global__ void __launch_bounds__(256, 2) k_gemm_mma(int toCat) {
    __shared__ uint32_t sA[2][128][12];   // [hi/lo][row][kp] bf16x2, stride-12 pad
    __shared__ uint32_t sB[2][128][12];   // [hi/lo][n][kp]
    int tid = threadIdx.x;
    int warp = tid >> 5, lane = tid & 31;
    int wm = warp & 3, wn = warp >> 2;        // 4 x 2 warp grid
    int bm = blockIdx.x * 128, bn = blockIdx.y * 128;
    int lr = lane >> 2, lq = lane & 3;

    float acc[2][8][4];
#pragma unroll
    for (int i = 0; i < 2; i++)
#pragma unroll
        for (int j = 0; j < 8; j++)
#pragma unroll
            for (int q = 0; q < 4; q++) acc[i][j][q] = 0.f;

    for (int c = 0; c < 16; c++) {
        // stage A: 128 rows x 16 k (8 kp) fp32 -> bf16 hi/lo pairs
#pragma unroll
        for (int it = 0; it < 4; it++) {
            int idx = it * 256 + tid;
            int row = idx >> 3, j = idx & 7;
            int m = bm + row;
            float2 v = (m < NN) ? *(const float2*)(d_cat + m * 256 + c * 16 + 2 * j)
                                : make_float2(0.f, 0.f);
            uint32_t hp, lp;
            asm("cvt.rn.bf16x2.f32 %0, %1, %2;" : "=r"(hp) : "f"(v.y), "f"(v.x));
            float h0 = __uint_as_float(hp << 16);
            float h1 = __uint_as_float(hp & 0xFFFF0000u);
            asm("cvt.rn.bf16x2.f32 %0, %1, %2;" : "=r"(lp) : "f"(v.y - h1), "f"(v.x - h0));
            sA[0][row][j] = hp;
            sA[1][row][j] = lp;
        }
        // stage B: 128 n x 8 kp from pre-split global
#pragma unroll
        for (int it = 0; it < 4; it++) {
            int idx = it * 256 + tid;
            int n = idx >> 3, j = idx & 7;
            sB[0][n][j] = d_Bhi[(bn + n) * 128 + c * 8 + j];
            sB[1][n][j] = d_Blo[(bn + n) * 128 + c * 8 + j];
        }
        __syncthreads();

        uint32_t ah[2][4], al[2][4];
#pragma unroll
        for (int mt = 0; mt < 2; mt++) {
            int r = wm * 32 + mt * 16 + lr;
            ah[mt][0] = sA[0][r][lq];     ah[mt][1] = sA[0][r + 8][lq];
            ah[mt][2] = sA[0][r][lq + 4]; ah[mt][3] = sA[0][r + 8][lq + 4];
            al[mt][0] = sA[1][r][lq];     al[mt][1] = sA[1][r + 8][lq];
            al[mt][2] = sA[1][r][lq + 4]; al[mt][3] = sA[1][r + 8][lq + 4];
        }
#pragma unroll
        for (int nt = 0; nt < 8; nt++) {
            int n = wn * 64 + nt * 8 + lr;
            uint32_t bh0 = sB[0][n][lq], bh1 = sB[0][n][lq + 4];
            uint32_t bl0 = sB[1][n][lq], bl1 = sB[1][n][lq + 4];
            mma16816(acc[0][nt], ah[0], bh0, bh1);
            mma16816(acc[0][nt], ah[0], bl0, bl1);
            mma16816(acc[0][nt], al[0], bh0, bh1);
            mma16816(acc[1][nt], ah[1], bh0, bh1);
            mma16816(acc[1][nt], ah[1], bl0, bl1);
            mma16816(acc[1][nt], al[1], bh0, bh1);
        }
        __syncthreads();
    }

    // epilogue: fold rank-1 + bias, ReLU, store
#pragma unroll
    for (int mt = 0; mt < 2; mt++) {
        int rbase = bm + wm * 32 + mt * 16 + lr;
#pragma unroll
        for (int half = 0; half < 2; half++) {
            int r = rbase + half * 8;
            if (r < NN) {
                float wsm = d_wsum[r];
#pragma unroll
                for (int nt = 0; nt < 8; nt++) {
                    int col = bn + wn * 64 + nt * 8 + 2 * lq;
                    float v0 = acc[mt][nt][half * 2 + 0] + d_b2[col] + wsm * d_u[col];
                    float v1 = acc[mt][nt][half * 2 + 1] + d_b2[col + 1] + wsm * d_u[col + 1];
                    v0 = v0 > 0.f ? v0 : 0.f;
                    v1 = v1 > 0.f ? v1 : 0.f;
                    float2 o = make_float2(v0, v1);
                    if (toCat) *(float2*)&d_cat[r * 256 + 128 + col] = o;
                    else       *(float2*)&d_act[r * 256 + col] = o;
                }
            }
        }
    }
}

// ---------------- column stats ----------------
__global__ void k_stats(int which, int F) {
    const float* base = which ? (const float*)d_act : (const float*)(d_cat + 128);
    int f = threadIdx.x;
    float s = 0.f, s2 = 0.f;
    for (int n = blockIdx.x; n < NN; n += gridDim.x) {
        float v = base[n * 256 + f];
        s += v;
        s2 += v * v;
    }
    atomicAdd(&d_stats[f], s);
    atomicAdd(&d_stats[256 + f], s2);
}

__global__ void k_mkbn(const float* __restrict__ gamma, const float* __restrict__ beta, int F) {
    int f = threadIdx.x;
    if (f >= F) return;
    float mu = d_stats[f] * (1.f / NN);
    float var = d_stats[256 + f] * (1.f / NN) - mu * mu;
    float sc = gamma[f] * rsqrtf(var + BN_EPS);
    d_scl[f] = sc;
    d_shl[f] = beta[f] - mu * sc;
}

__global__ void k_pool(float* __restrict__ out) {
    int g = blockIdx.x, f = threadIdx.x;
    int n0 = d_goff[g], n1 = d_goff[g + 1];
    float s = 0.f;
    for (int n = n0; n < n1; n++) s += d_act[n * 256 + f];
    out[g * 256 + f] = d_scl[f] * s + (float)(n1 - n0) * d_shl[f];
}

// ---------------- launch ----------------
extern "C" void kernel_launch(void* const* d_in, const int* in_sizes, int n_in,
                              void* d_out, int out_size) {
    const float* x   = (const float*)d_in[0];
    const void*  ei  = d_in[1];
    const void*  bat = d_in[2];
    const float* Wi  = (const float*)d_in[3];
    const float* Wr  = (const float*)d_in[4];
    const float* b   = (const float*)d_in[5];
    const float* g   = (const float*)d_in[6];
    const float* be  = (const float*)d_in[7];
    const float* Wi6 = (const float*)d_in[8];
    const float* Wr6 = (const float*)d_in[9];
    const float* b6  = (const float*)d_in[10];
    const float* g6  = (const float*)d_in[11];
    const float* be6 = (const float*)d_in[12];
    float* out = (float*)d_out;

    k_detect<<<1, 256>>>((const unsigned int*)ei);
    k_extract_copy<<<(NN * 32 + 255) / 256, 256>>>(ei, x);
    k_count<<<(EE + 255) / 256, 256>>>();
    k_scan1<<<NB, 256>>>();
    k_scan2<<<1, 512>>>();
    k_scan3<<<NB, 256>>>();
    k_fill<<<(EE + 255) / 256, 256>>>();
    k_wsum<<<(NN + 7) / 8, 256>>>();
    k_wcat<<<(5 * 32768 + 65536 + 255) / 256, 256>>>(Wi, Wr, Wi6, Wr6);
    k_goff<<<(NN + 255) / 256, 256>>>(bat);

    const int mblocks = (NN + 127) / 128;  // 782
    for (int l = 0; l < 5; l++) {
        k_spmm<<<(NN + 7) / 8, 256>>>();
        k_bnfold<<<1, 256>>>(g + (l - 1) * 128, be + (l - 1) * 128, b + l * 128, 128, l == 0);
        k_scaleBsplit<<<128, 256>>>(l * 32768, 128);
        k_mkub_par<<<16, 128>>>(Wi + l * 16384, Wr + l * 16384, 128);
        k_gemm_mma<<<dim3(mblocks, 1), 256>>>(1);
        k_stats<<<512, 128>>>(0, 128);
    }
    // layer 6 (F_OUT = 256)
    k_spmm<<<(NN + 7) / 8, 256>>>();
    k_bnfold<<<1, 256>>>(g + 4 * 128, be + 4 * 128, b6, 256, 0);
    k_scaleBsplit<<<256, 256>>>(5 * 32768, 256);
    k_mkub_par<<<16, 256>>>(Wi6, Wr6, 256);
    k_gemm_mma<<<dim3(mblocks, 2), 256>>>(0);
    k_stats<<<512, 256>>>(1, 256);

    k_mkbn<<<1, 256>>>(g6, be6, 256);
    k_pool<<<GG, 256>>>(out);
}